// round 4
// baseline (speedup 1.0000x reference)
#include <cuda_runtime.h>
#include <math.h>

#define NMB  4
#define CNUM 17
#define HNUM 8
#define BNUM 8
#define SLEN 512
#define DDIM 64
#define TI   64          // rows per block
#define JT   128         // j chunk per class pass
#define KSTR 68          // Ks row stride (floats): conflict-free, 16B-aligned rows
#define USTRD 68         // U row stride

// Premixed W1_^T: [C][h][n][m]  (transposed so a W column is contiguous)
__device__ float g_W[CNUM * HNUM * DDIM * DDIM];

// ---- packed f32x2 helpers ----
union F4U   { float4 f4; unsigned long long u[2]; };
union U64F2 { unsigned long long u; float2 f; };

__device__ __forceinline__ void ffma2(unsigned long long& d,
                                      unsigned long long a,
                                      unsigned long long b) {
    asm("fma.rn.f32x2 %0, %1, %2, %0;" : "+l"(d) : "l"(a), "l"(b));
}
__device__ __forceinline__ float hadd2(unsigned long long a) {
    U64F2 x; x.u = a; return x.f.x + x.f.y;
}

// ---------------- Kernel 1: W^T[c,h][n][m] = sum_B softmax(alpha1)[c,B,h] * W1[B,h][m][n]
__global__ void wmix_kernel(const float* __restrict__ W1,
                            const float* __restrict__ alpha1) {
    int c = blockIdx.x;   // 0..16
    int h = blockIdx.y;   // 0..7
    float a[NMB];
#pragma unroll
    for (int B = 0; B < NMB; B++) a[B] = alpha1[(c * NMB + B) * HNUM + h];
    float mx = fmaxf(fmaxf(a[0], a[1]), fmaxf(a[2], a[3]));
    float w[NMB], s = 0.f;
#pragma unroll
    for (int B = 0; B < NMB; B++) { w[B] = __expf(a[B] - mx); s += w[B]; }
    float inv = 1.f / s;
#pragma unroll
    for (int B = 0; B < NMB; B++) w[B] *= inv;

    float* dst = g_W + (c * HNUM + h) * DDIM * DDIM;
    const float* src = W1 + h * DDIM * DDIM;
    for (int e = threadIdx.x; e < DDIM * DDIM; e += blockDim.x) {
        int m = e >> 6, nn = e & 63;
        float v = 0.f;
#pragma unroll
        for (int B = 0; B < NMB; B++) v += w[B] * src[B * HNUM * DDIM * DDIM + e];
        dst[nn * DDIM + m] = v;   // transposed store
    }
}

// ---------------- Kernel 2: fused scores ----------------
// shared layout (bytes):
#define OFF_QS   0                           // 16384
#define OFF_U    16384                       // 64*68*4 = 17408
#define OFF_KS   (16384 + 17408)             // 128*68*4 = 34816
#define OFF_INT  (OFF_KS + 34816)
// ints: bj_all[512], jperm[512], jcnt[8], joff[8], jpos[8], rcnt[8], rlist[256]
#define SMEM_BYTES (OFF_INT + (512 + 512 + 8 + 8 + 8 + 8 + 256) * 4)

__global__ __launch_bounds__(256, 2)
void mb_scores_kernel(const float* __restrict__ q,
                      const float* __restrict__ k,
                      const int*   __restrict__ bseq,
                      float* __restrict__ out) {
    extern __shared__ unsigned char smraw[];
    float* Qs = (float*)(smraw + OFF_QS);
    float* Us = (float*)(smraw + OFF_U);
    float* Ks = (float*)(smraw + OFF_KS);
    int*   bj_all = (int*)(smraw + OFF_INT);
    int*   jperm  = bj_all + 512;
    int*   jcnt   = jperm + 512;
    int*   joff   = jcnt + 8;
    int*   jpos   = joff + 8;
    int*   rcnt   = jpos + 8;
    int*   rlist  = rcnt + 8;

    const int tid = threadIdx.x;
    const int it  = blockIdx.x;
    const int h   = blockIdx.y;
    const int b   = blockIdx.z;
    const int i0  = it * TI;

    const float* qbase = q + ((size_t)(b * HNUM + h) * SLEN + i0) * DDIM;
    const float* kbase = k + ((size_t)(b * HNUM + h) * SLEN) * DDIM;

    // load Q tile (64x64) as float4
    for (int t = tid; t < TI * DDIM / 4; t += 256)
        ((float4*)Qs)[t] = ((const float4*)qbase)[t];
    // load b_seq row
    for (int t = tid; t < SLEN; t += 256) bj_all[t] = bseq[b * SLEN + t];
    if (tid < 8) { jcnt[tid] = 0; rcnt[tid] = 0; }
    __syncthreads();

    // column class histogram
    for (int t = tid; t < SLEN; t += 256) atomicAdd(&jcnt[bj_all[t]], 1);
    __syncthreads();
    if (tid == 0) {
        int s = 0;
        for (int t = 0; t < 5; t++) { joff[t] = s; jpos[t] = s; s += jcnt[t]; }
    }
    __syncthreads();
    // column permutation grouped by class
    for (int t = tid; t < SLEN; t += 256) {
        int c = bj_all[t];
        int p = atomicAdd(&jpos[c], 1);
        jperm[p] = t;
    }
    // row lists grouped by bi value 1..4
    for (int t = tid; t < TI; t += 256) {
        int c = bj_all[i0 + t];
        if (c > 0) { int p = atomicAdd(&rcnt[c - 1], 1); rlist[(c - 1) * 64 + p] = t; }
    }
    __syncthreads();

    const int n = tid & 63;
    const int g = tid >> 6;   // 0..3

    // ---------------- Phase A0: slot0 for all 64 rows (4 rows / iter) ----
    {
        const F4U* Wt = (const F4U*)(g_W + (size_t)h * DDIM * DDIM + n * DDIM); // c=0
        unsigned long long wp[32];
#pragma unroll
        for (int qd = 0; qd < 16; qd++) {
            F4U w4 = Wt[qd];
            wp[2 * qd] = w4.u[0]; wp[2 * qd + 1] = w4.u[1];
        }
#pragma unroll
        for (int r = 0; r < 16; r += 4) {
            int i = g * 16 + r;
            const F4U* q0 = (const F4U*)(Qs + (i + 0) * DDIM);
            const F4U* q1 = (const F4U*)(Qs + (i + 1) * DDIM);
            const F4U* q2 = (const F4U*)(Qs + (i + 2) * DDIM);
            const F4U* q3 = (const F4U*)(Qs + (i + 3) * DDIM);
            unsigned long long a0 = 0, a1 = 0, b0 = 0, b1 = 0;
            unsigned long long c0 = 0, c1 = 0, d0 = 0, d1 = 0;
#pragma unroll
            for (int mb = 0; mb < 16; mb++) {
                F4U v0 = q0[mb], v1 = q1[mb], v2 = q2[mb], v3 = q3[mb];
                ffma2(a0, v0.u[0], wp[2 * mb]); ffma2(a1, v0.u[1], wp[2 * mb + 1]);
                ffma2(b0, v1.u[0], wp[2 * mb]); ffma2(b1, v1.u[1], wp[2 * mb + 1]);
                ffma2(c0, v2.u[0], wp[2 * mb]); ffma2(c1, v2.u[1], wp[2 * mb + 1]);
                ffma2(d0, v3.u[0], wp[2 * mb]); ffma2(d1, v3.u[1], wp[2 * mb + 1]);
            }
            Us[(i + 0) * USTRD + n] = hadd2(a0) + hadd2(a1);
            Us[(i + 1) * USTRD + n] = hadd2(b0) + hadd2(b1);
            Us[(i + 2) * USTRD + n] = hadd2(c0) + hadd2(c1);
            Us[(i + 3) * USTRD + n] = hadd2(d0) + hadd2(d1);
        }
    }

    // ---------------- class passes ----------------
    const int tx = tid & 31, ty = tid >> 5;   // 32 x 8
    float* outbase = out + ((size_t)(b * HNUM + h) * SLEN + i0) * SLEN;

    int prevClass = 0;
    for (int t = 0; t < 5; t++) {
        int nt  = jcnt[t];
        int off = joff[t];
        if (nt == 0) continue;

        // class transition: recompute U rows with bi>0 for class t
        if (t > 0 && t != prevClass) {
            __syncthreads();   // prior pass readers done
            int v   = g + 1;              // this group's bi value
            int cnt = rcnt[v - 1];
            if (cnt > 0) {
                int cc = 4 * (v - 1) + t;  // 1..16
                const F4U* Wt = (const F4U*)(g_W + (size_t)(cc * HNUM + h) * DDIM * DDIM + n * DDIM);
                unsigned long long wp[32];
#pragma unroll
                for (int qd = 0; qd < 16; qd++) {
                    F4U w4 = Wt[qd];
                    wp[2 * qd] = w4.u[0]; wp[2 * qd + 1] = w4.u[1];
                }
                int r = 0;
                for (; r + 3 < cnt; r += 4) {
                    int ia = rlist[(v - 1) * 64 + r];
                    int ib = rlist[(v - 1) * 64 + r + 1];
                    int ic = rlist[(v - 1) * 64 + r + 2];
                    int id = rlist[(v - 1) * 64 + r + 3];
                    const F4U* q0 = (const F4U*)(Qs + ia * DDIM);
                    const F4U* q1 = (const F4U*)(Qs + ib * DDIM);
                    const F4U* q2 = (const F4U*)(Qs + ic * DDIM);
                    const F4U* q3 = (const F4U*)(Qs + id * DDIM);
                    unsigned long long a0 = 0, a1 = 0, b0 = 0, b1 = 0;
                    unsigned long long c0 = 0, c1 = 0, d0 = 0, d1 = 0;
#pragma unroll
                    for (int mb = 0; mb < 16; mb++) {
                        F4U v0 = q0[mb], v1 = q1[mb], v2 = q2[mb], v3 = q3[mb];
                        ffma2(a0, v0.u[0], wp[2 * mb]); ffma2(a1, v0.u[1], wp[2 * mb + 1]);
                        ffma2(b0, v1.u[0], wp[2 * mb]); ffma2(b1, v1.u[1], wp[2 * mb + 1]);
                        ffma2(c0, v2.u[0], wp[2 * mb]); ffma2(c1, v2.u[1], wp[2 * mb + 1]);
                        ffma2(d0, v3.u[0], wp[2 * mb]); ffma2(d1, v3.u[1], wp[2 * mb + 1]);
                    }
                    Us[ia * USTRD + n] = hadd2(a0) + hadd2(a1);
                    Us[ib * USTRD + n] = hadd2(b0) + hadd2(b1);
                    Us[ic * USTRD + n] = hadd2(c0) + hadd2(c1);
                    Us[id * USTRD + n] = hadd2(d0) + hadd2(d1);
                }
                for (; r < cnt; r++) {
                    int ia = rlist[(v - 1) * 64 + r];
                    const F4U* q0 = (const F4U*)(Qs + ia * DDIM);
                    unsigned long long a0 = 0, a1 = 0;
#pragma unroll
                    for (int mb = 0; mb < 16; mb++) {
                        F4U v0 = q0[mb];
                        ffma2(a0, v0.u[0], wp[2 * mb]);
                        ffma2(a1, v0.u[1], wp[2 * mb + 1]);
                    }
                    Us[ia * USTRD + n] = hadd2(a0) + hadd2(a1);
                }
            }
            prevClass = t;
        }

        for (int j0 = 0; j0 < nt; j0 += JT) {
            int chunk = nt - j0; if (chunk > JT) chunk = JT;
            __syncthreads();   // Ks reuse safety + U visibility
            // gather K chunk rows (coalesced 256B rows)
            for (int x = tid; x < JT * 16; x += 256) {
                int r = x >> 4, mb = x & 15;
                float4 v;
                if (r < chunk) v = ((const float4*)(kbase + (size_t)jperm[off + j0 + r] * DDIM))[mb];
                else           v = make_float4(0.f, 0.f, 0.f, 0.f);
                *(float4*)(Ks + r * KSTR + mb * 4) = v;
            }
            __syncthreads();

            // register tile: 8 rows (stride 8) x 4 cols (stride 32), packed acc
            unsigned long long acc[8][4];
#pragma unroll
            for (int ii = 0; ii < 8; ii++)
#pragma unroll
                for (int jj = 0; jj < 4; jj++) acc[ii][jj] = 0ull;

#pragma unroll
            for (int mb = 0; mb < 16; mb++) {
                F4U kv[4];
#pragma unroll
                for (int jj = 0; jj < 4; jj++)
                    kv[jj].f4 = *(const float4*)(Ks + (tx + jj * 32) * KSTR + mb * 4);
#pragma unroll
                for (int ii = 0; ii < 8; ii++) {
                    F4U av;
                    av.f4 = *(const float4*)(Us + (ty + ii * 8) * USTRD + mb * 4);
#pragma unroll
                    for (int jj = 0; jj < 4; jj++) {
                        ffma2(acc[ii][jj], av.u[0], kv[jj].u[0]);
                        ffma2(acc[ii][jj], av.u[1], kv[jj].u[1]);
                    }
                }
            }
            // scattered stores (L2 write-coalesced)
#pragma unroll
            for (int jj = 0; jj < 4; jj++) {
                int jc = tx + jj * 32;
                if (j0 + jc < nt) {
                    int jp = jperm[off + j0 + jc];
#pragma unroll
                    for (int ii = 0; ii < 8; ii++)
                        outbase[(size_t)(ty + ii * 8) * SLEN + jp] = hadd2(acc[ii][jj]);
                }
            }
        }
    }
}

// ---------------- launch ----------------
extern "C" void kernel_launch(void* const* d_in, const int* in_sizes, int n_in,
                              void* d_out, int out_size) {
    const float* q      = (const float*)d_in[0];
    const float* kk     = (const float*)d_in[1];
    const int*   bseq   = (const int*)  d_in[2];
    const float* W1     = (const float*)d_in[3];
    const float* alpha1 = (const float*)d_in[4];
    float* out = (float*)d_out;

    cudaFuncSetAttribute(mb_scores_kernel,
                         cudaFuncAttributeMaxDynamicSharedMemorySize, SMEM_BYTES);

    dim3 g1(CNUM, HNUM);
    wmix_kernel<<<g1, 256>>>(W1, alpha1);

    dim3 g2(SLEN / TI, HNUM, BNUM);   // 512 blocks
    mb_scores_kernel<<<g2, 256, SMEM_BYTES>>>(q, kk, bseq, out);
}

// round 5
// speedup vs baseline: 1.0051x; 1.0051x over previous
#include <cuda_runtime.h>
#include <math.h>

#define NMB  4
#define CNUM 17
#define HNUM 8
#define BNUM 8
#define SLEN 512
#define DDIM 64
#define TI   64          // rows per block
#define JT   128         // j chunk per class pass
#define KSTR 68          // Ks row stride (floats): conflict-free, 16B-aligned rows
#define USTRD 68         // U row stride

// Premixed W1_^T: [C][h][n][m]  (transposed so a W column is contiguous)
__device__ float g_W[CNUM * HNUM * DDIM * DDIM];

// ---- packed f32x2 helpers ----
union F4U   { float4 f4; unsigned long long u[2]; };
union U64F2 { unsigned long long u; float2 f; };

__device__ __forceinline__ void ffma2(unsigned long long& d,
                                      unsigned long long a,
                                      unsigned long long b) {
    asm("fma.rn.f32x2 %0, %1, %2, %0;" : "+l"(d) : "l"(a), "l"(b));
}
__device__ __forceinline__ float hadd2(unsigned long long a) {
    U64F2 x; x.u = a; return x.f.x + x.f.y;
}

// ---------------- Kernel 1: W^T[c,h][n][m] = sum_B softmax(alpha1)[c,B,h] * W1[B,h][m][n]
__global__ void wmix_kernel(const float* __restrict__ W1,
                            const float* __restrict__ alpha1) {
    int c = blockIdx.x;   // 0..16
    int h = blockIdx.y;   // 0..7
    float a[NMB];
#pragma unroll
    for (int B = 0; B < NMB; B++) a[B] = alpha1[(c * NMB + B) * HNUM + h];
    float mx = fmaxf(fmaxf(a[0], a[1]), fmaxf(a[2], a[3]));
    float w[NMB], s = 0.f;
#pragma unroll
    for (int B = 0; B < NMB; B++) { w[B] = __expf(a[B] - mx); s += w[B]; }
    float inv = 1.f / s;
#pragma unroll
    for (int B = 0; B < NMB; B++) w[B] *= inv;

    float* dst = g_W + (c * HNUM + h) * DDIM * DDIM;
    const float* src = W1 + h * DDIM * DDIM;
    for (int e = threadIdx.x; e < DDIM * DDIM; e += blockDim.x) {
        int m = e >> 6, nn = e & 63;
        float v = 0.f;
#pragma unroll
        for (int B = 0; B < NMB; B++) v += w[B] * src[B * HNUM * DDIM * DDIM + e];
        dst[nn * DDIM + m] = v;   // transposed store
    }
}

// ---------------- Kernel 2: fused scores ----------------
// shared layout (bytes):
#define OFF_QS   0                           // 16384
#define OFF_U    16384                       // 64*68*4 = 17408
#define OFF_KS   (16384 + 17408)             // 128*68*4 = 34816
#define OFF_INT  (OFF_KS + 34816)
// ints: bj_all[512], jperm[512], jcnt[8], joff[8], jpos[8], rcnt[8], rlist[256]
#define SMEM_BYTES (OFF_INT + (512 + 512 + 8 + 8 + 8 + 8 + 256) * 4)

__global__ __launch_bounds__(256, 2)
void mb_scores_kernel(const float* __restrict__ q,
                      const float* __restrict__ k,
                      const int*   __restrict__ bseq,
                      float* __restrict__ out) {
    extern __shared__ unsigned char smraw[];
    float* Qs = (float*)(smraw + OFF_QS);
    float* Us = (float*)(smraw + OFF_U);
    float* Ks = (float*)(smraw + OFF_KS);
    int*   bj_all = (int*)(smraw + OFF_INT);
    int*   jperm  = bj_all + 512;
    int*   jcnt   = jperm + 512;
    int*   joff   = jcnt + 8;
    int*   jpos   = joff + 8;
    int*   rcnt   = jpos + 8;
    int*   rlist  = rcnt + 8;

    const int tid = threadIdx.x;
    const int it  = blockIdx.x;
    const int h   = blockIdx.y;
    const int b   = blockIdx.z;
    const int i0  = it * TI;

    const float* qbase = q + ((size_t)(b * HNUM + h) * SLEN + i0) * DDIM;
    const float* kbase = k + ((size_t)(b * HNUM + h) * SLEN) * DDIM;

    // load Q tile (64x64) as float4
    for (int t = tid; t < TI * DDIM / 4; t += 256)
        ((float4*)Qs)[t] = ((const float4*)qbase)[t];
    // load b_seq row
    for (int t = tid; t < SLEN; t += 256) bj_all[t] = bseq[b * SLEN + t];
    if (tid < 8) { jcnt[tid] = 0; rcnt[tid] = 0; }
    __syncthreads();

    // column class histogram
    for (int t = tid; t < SLEN; t += 256) atomicAdd(&jcnt[bj_all[t]], 1);
    __syncthreads();
    if (tid == 0) {
        int s = 0;
        for (int t = 0; t < 5; t++) { joff[t] = s; jpos[t] = s; s += jcnt[t]; }
    }
    __syncthreads();
    // column permutation grouped by class
    for (int t = tid; t < SLEN; t += 256) {
        int c = bj_all[t];
        int p = atomicAdd(&jpos[c], 1);
        jperm[p] = t;
    }
    // row lists grouped by bi value 1..4
    for (int t = tid; t < TI; t += 256) {
        int c = bj_all[i0 + t];
        if (c > 0) { int p = atomicAdd(&rcnt[c - 1], 1); rlist[(c - 1) * 64 + p] = t; }
    }
    __syncthreads();

    const int n = tid & 63;
    const int g = tid >> 6;   // 0..3

    // ---------------- Phase A0: slot0 for all 64 rows (4 rows / iter) ----
    {
        const F4U* Wt = (const F4U*)(g_W + (size_t)h * DDIM * DDIM + n * DDIM); // c=0
        unsigned long long wp[32];
#pragma unroll
        for (int qd = 0; qd < 16; qd++) {
            F4U w4 = Wt[qd];
            wp[2 * qd] = w4.u[0]; wp[2 * qd + 1] = w4.u[1];
        }
#pragma unroll
        for (int r = 0; r < 16; r += 4) {
            int i = g * 16 + r;
            const F4U* q0 = (const F4U*)(Qs + (i + 0) * DDIM);
            const F4U* q1 = (const F4U*)(Qs + (i + 1) * DDIM);
            const F4U* q2 = (const F4U*)(Qs + (i + 2) * DDIM);
            const F4U* q3 = (const F4U*)(Qs + (i + 3) * DDIM);
            unsigned long long a0 = 0, a1 = 0, b0 = 0, b1 = 0;
            unsigned long long c0 = 0, c1 = 0, d0 = 0, d1 = 0;
#pragma unroll
            for (int mb = 0; mb < 16; mb++) {
                F4U v0 = q0[mb], v1 = q1[mb], v2 = q2[mb], v3 = q3[mb];
                ffma2(a0, v0.u[0], wp[2 * mb]); ffma2(a1, v0.u[1], wp[2 * mb + 1]);
                ffma2(b0, v1.u[0], wp[2 * mb]); ffma2(b1, v1.u[1], wp[2 * mb + 1]);
                ffma2(c0, v2.u[0], wp[2 * mb]); ffma2(c1, v2.u[1], wp[2 * mb + 1]);
                ffma2(d0, v3.u[0], wp[2 * mb]); ffma2(d1, v3.u[1], wp[2 * mb + 1]);
            }
            Us[(i + 0) * USTRD + n] = hadd2(a0) + hadd2(a1);
            Us[(i + 1) * USTRD + n] = hadd2(b0) + hadd2(b1);
            Us[(i + 2) * USTRD + n] = hadd2(c0) + hadd2(c1);
            Us[(i + 3) * USTRD + n] = hadd2(d0) + hadd2(d1);
        }
    }

    // ---------------- class passes ----------------
    const int tx = tid & 31, ty = tid >> 5;   // 32 x 8
    float* outbase = out + ((size_t)(b * HNUM + h) * SLEN + i0) * SLEN;

    int prevClass = 0;
    for (int t = 0; t < 5; t++) {
        int nt  = jcnt[t];
        int off = joff[t];
        if (nt == 0) continue;

        // class transition: recompute U rows with bi>0 for class t
        if (t > 0 && t != prevClass) {
            __syncthreads();   // prior pass readers done
            int v   = g + 1;              // this group's bi value
            int cnt = rcnt[v - 1];
            if (cnt > 0) {
                int cc = 4 * (v - 1) + t;  // 1..16
                const F4U* Wt = (const F4U*)(g_W + (size_t)(cc * HNUM + h) * DDIM * DDIM + n * DDIM);
                unsigned long long wp[32];
#pragma unroll
                for (int qd = 0; qd < 16; qd++) {
                    F4U w4 = Wt[qd];
                    wp[2 * qd] = w4.u[0]; wp[2 * qd + 1] = w4.u[1];
                }
                int r = 0;
                for (; r + 3 < cnt; r += 4) {
                    int ia = rlist[(v - 1) * 64 + r];
                    int ib = rlist[(v - 1) * 64 + r + 1];
                    int ic = rlist[(v - 1) * 64 + r + 2];
                    int id = rlist[(v - 1) * 64 + r + 3];
                    const F4U* q0 = (const F4U*)(Qs + ia * DDIM);
                    const F4U* q1 = (const F4U*)(Qs + ib * DDIM);
                    const F4U* q2 = (const F4U*)(Qs + ic * DDIM);
                    const F4U* q3 = (const F4U*)(Qs + id * DDIM);
                    unsigned long long a0 = 0, a1 = 0, b0 = 0, b1 = 0;
                    unsigned long long c0 = 0, c1 = 0, d0 = 0, d1 = 0;
#pragma unroll
                    for (int mb = 0; mb < 16; mb++) {
                        F4U v0 = q0[mb], v1 = q1[mb], v2 = q2[mb], v3 = q3[mb];
                        ffma2(a0, v0.u[0], wp[2 * mb]); ffma2(a1, v0.u[1], wp[2 * mb + 1]);
                        ffma2(b0, v1.u[0], wp[2 * mb]); ffma2(b1, v1.u[1], wp[2 * mb + 1]);
                        ffma2(c0, v2.u[0], wp[2 * mb]); ffma2(c1, v2.u[1], wp[2 * mb + 1]);
                        ffma2(d0, v3.u[0], wp[2 * mb]); ffma2(d1, v3.u[1], wp[2 * mb + 1]);
                    }
                    Us[ia * USTRD + n] = hadd2(a0) + hadd2(a1);
                    Us[ib * USTRD + n] = hadd2(b0) + hadd2(b1);
                    Us[ic * USTRD + n] = hadd2(c0) + hadd2(c1);
                    Us[id * USTRD + n] = hadd2(d0) + hadd2(d1);
                }
                for (; r < cnt; r++) {
                    int ia = rlist[(v - 1) * 64 + r];
                    const F4U* q0 = (const F4U*)(Qs + ia * DDIM);
                    unsigned long long a0 = 0, a1 = 0;
#pragma unroll
                    for (int mb = 0; mb < 16; mb++) {
                        F4U v0 = q0[mb];
                        ffma2(a0, v0.u[0], wp[2 * mb]);
                        ffma2(a1, v0.u[1], wp[2 * mb + 1]);
                    }
                    Us[ia * USTRD + n] = hadd2(a0) + hadd2(a1);
                }
            }
            prevClass = t;
        }

        for (int j0 = 0; j0 < nt; j0 += JT) {
            int chunk = nt - j0; if (chunk > JT) chunk = JT;
            __syncthreads();   // Ks reuse safety + U visibility
            // gather K chunk rows (coalesced 256B rows)
            for (int x = tid; x < JT * 16; x += 256) {
                int r = x >> 4, mb = x & 15;
                float4 v;
                if (r < chunk) v = ((const float4*)(kbase + (size_t)jperm[off + j0 + r] * DDIM))[mb];
                else           v = make_float4(0.f, 0.f, 0.f, 0.f);
                *(float4*)(Ks + r * KSTR + mb * 4) = v;
            }
            __syncthreads();

            // register tile: 8 rows (stride 8) x 4 cols (stride 32), packed acc
            unsigned long long acc[8][4];
#pragma unroll
            for (int ii = 0; ii < 8; ii++)
#pragma unroll
                for (int jj = 0; jj < 4; jj++) acc[ii][jj] = 0ull;

#pragma unroll
            for (int mb = 0; mb < 16; mb++) {
                F4U kv[4];
#pragma unroll
                for (int jj = 0; jj < 4; jj++)
                    kv[jj].f4 = *(const float4*)(Ks + (tx + jj * 32) * KSTR + mb * 4);
#pragma unroll
                for (int ii = 0; ii < 8; ii++) {
                    F4U av;
                    av.f4 = *(const float4*)(Us + (ty + ii * 8) * USTRD + mb * 4);
#pragma unroll
                    for (int jj = 0; jj < 4; jj++) {
                        ffma2(acc[ii][jj], av.u[0], kv[jj].u[0]);
                        ffma2(acc[ii][jj], av.u[1], kv[jj].u[1]);
                    }
                }
            }
            // scattered stores (L2 write-coalesced)
#pragma unroll
            for (int jj = 0; jj < 4; jj++) {
                int jc = tx + jj * 32;
                if (j0 + jc < nt) {
                    int jp = jperm[off + j0 + jc];
#pragma unroll
                    for (int ii = 0; ii < 8; ii++)
                        outbase[(size_t)(ty + ii * 8) * SLEN + jp] = hadd2(acc[ii][jj]);
                }
            }
        }
    }
}

// ---------------- launch ----------------
extern "C" void kernel_launch(void* const* d_in, const int* in_sizes, int n_in,
                              void* d_out, int out_size) {
    const float* q      = (const float*)d_in[0];
    const float* kk     = (const float*)d_in[1];
    const int*   bseq   = (const int*)  d_in[2];
    const float* W1     = (const float*)d_in[3];
    const float* alpha1 = (const float*)d_in[4];
    float* out = (float*)d_out;

    cudaFuncSetAttribute(mb_scores_kernel,
                         cudaFuncAttributeMaxDynamicSharedMemorySize, SMEM_BYTES);

    dim3 g1(CNUM, HNUM);
    wmix_kernel<<<g1, 256>>>(W1, alpha1);

    dim3 g2(SLEN / TI, HNUM, BNUM);   // 512 blocks
    mb_scores_kernel<<<g2, 256, SMEM_BYTES>>>(q, kk, bseq, out);
}